// round 5
// baseline (speedup 1.0000x reference)
#include <cuda_runtime.h>
#include <math.h>

// Problem constants
#define NSER 4096
#define NTT  400
#define OO   9
// log(2*pi)
#define LOG2PI 1.8378770664093453f

// scratch for per-series log-likelihood (no allocations allowed)
__device__ float g_ll[NSER];

__global__ __launch_bounds__(32)
void kf_kernel(const float* __restrict__ y,
               const float* __restrict__ B1,
               const float* __restrict__ b2p,
               const float* __restrict__ l1f,
               const float* __restrict__ l2f,
               const float* __restrict__ logq,
               const float* __restrict__ logr,
               const float* __restrict__ g0p,
               const float* __restrict__ gcp,
               float* __restrict__ out)
{
    const int n = blockIdx.x * 32 + threadIdx.x;
    if (n >= NSER) return;

    // ---------------- per-thread constant precompute (identical across threads, ~trivial) ------
    float Bm[9];
#pragma unroll
    for (int i = 0; i < 9; i++) Bm[i] = B1[i];
    const float b2 = b2p[0];

    const float w1 = l1f[0], w2 = l1f[1], w4 = l1f[2], w5 = l1f[3], w7 = l1f[4], w8 = l1f[5];
    float w[9];
    w[0] = 1.f; w[1] = w1; w[2] = w2; w[3] = 1.f; w[4] = w4; w[5] = w5; w[6] = 1.f; w[7] = w7; w[8] = w8;
    float u[9];
    u[0] = 1.f;
#pragma unroll
    for (int i = 1; i < 9; i++) u[i] = l2f[i - 1];

    const float qv0 = expf(logq[0]);
    const float qv1 = expf(logq[1]);
    const float qv2 = expf(logq[2]);
    const float qv3 = expf(logq[3]);

    float Di[9], WD[9], du[9];
    float G0 = 0.f, G1 = 0.f, G2 = 0.f;
    float GR0 = 0.f, GR1 = 0.f, GR2 = 0.f;
    float logdetD = 0.f, alpha = 0.f, rho = 0.f;
#pragma unroll
    for (int o = 0; o < 9; o++) {
        float rv = expf(logr[o]);
        float Dv = rv + 1e-6f;
        float di = 1.0f / Dv;
        Di[o] = di;
        logdetD += logf(Dv);
        WD[o] = w[o] * di;
        float gterm  = w[o] * w[o] * di;
        float grterm = w[o] * w[o] * rv * di * di;
        if (o < 3)      { G0 += gterm; GR0 += grterm; }
        else if (o < 6) { G1 += gterm; GR1 += grterm; }
        else            { G2 += gterm; GR2 += grterm; }
        du[o] = u[o] * di;
        alpha += u[o] * u[o] * di;
        rho   += u[o] * u[o] * rv * di * di;
    }
    const float Cll = -0.5f * 9.0f * LOG2PI - 0.5f * logdetD;
    const float g0 = g0p[0], gc0 = gcp[0], gc1 = gcp[1], gc2 = gcp[2];

    // ---------------- state init ----------------
    float e0 = 0.f, e1 = 0.f, e2 = 0.f, e3 = 0.f;
    float p00 = 1000.f, p01 = 0.f, p02 = 0.f, p03 = 0.f;
    float p11v = 1000.f, p12 = 0.f, p13 = 0.f;
    float p22 = 1000.f, p23 = 0.f, p33 = 1000.f;
    float pr0v = 0.99f, pr1v = 0.01f;
    float llacc = 0.f;

    const float* yrow = y + (size_t)n * (NTT * OO);
    float* probs_base = out + 1;
    float* yp_base = out + 1 + (size_t)NSER * NTT * 2;

    float yv[9];
#pragma unroll
    for (int o = 0; o < 9; o++) yv[o] = yrow[o];

#pragma unroll 1
    for (int t = 0; t < NTT; t++) {
        // prefetch next timestep's observations (hide DRAM latency)
        float yn[9];
        if (t + 1 < NTT) {
            const float* yp = yrow + (t + 1) * 9;
#pragma unroll
            for (int o = 0; o < 9; o++) yn[o] = yp[o];
        }

        // regime-1 stay probability from current filtered state
        float xg = g0 + gc0 * e0 + gc1 * e1 + gc2 * e2;
        float p11s = 1.0f / (1.0f + expf(-xg));

        // ---------- predict: eta_pred = B eta ; P_pred = B P B^T + Q (B block-diag 3x3 & 1x1) ----------
        float ep0 = Bm[0] * e0 + Bm[1] * e1 + Bm[2] * e2;
        float ep1 = Bm[3] * e0 + Bm[4] * e1 + Bm[5] * e2;
        float ep2 = Bm[6] * e0 + Bm[7] * e1 + Bm[8] * e2;
        float ep3 = b2 * e3;

        float T00 = Bm[0] * p00 + Bm[1] * p01 + Bm[2] * p02;
        float T01 = Bm[0] * p01 + Bm[1] * p11v + Bm[2] * p12;
        float T02 = Bm[0] * p02 + Bm[1] * p12 + Bm[2] * p22;
        float T10 = Bm[3] * p00 + Bm[4] * p01 + Bm[5] * p02;
        float T11 = Bm[3] * p01 + Bm[4] * p11v + Bm[5] * p12;
        float T12 = Bm[3] * p02 + Bm[4] * p12 + Bm[5] * p22;
        float T20 = Bm[6] * p00 + Bm[7] * p01 + Bm[8] * p02;
        float T21 = Bm[6] * p01 + Bm[7] * p11v + Bm[8] * p12;
        float T22 = Bm[6] * p02 + Bm[7] * p12 + Bm[8] * p22;

        float s00 = T00 * Bm[0] + T01 * Bm[1] + T02 * Bm[2] + qv0;
        float s01 = T00 * Bm[3] + T01 * Bm[4] + T02 * Bm[5];
        float s02 = T00 * Bm[6] + T01 * Bm[7] + T02 * Bm[8];
        float s11 = T10 * Bm[3] + T11 * Bm[4] + T12 * Bm[5] + qv1;
        float s12 = T10 * Bm[6] + T11 * Bm[7] + T12 * Bm[8];
        float s22 = T20 * Bm[6] + T21 * Bm[7] + T22 * Bm[8] + qv2;
        float s03 = b2 * (Bm[0] * p03 + Bm[1] * p13 + Bm[2] * p23);
        float s13 = b2 * (Bm[3] * p03 + Bm[4] * p13 + Bm[5] * p23);
        float s23 = b2 * (Bm[6] * p03 + Bm[7] * p13 + Bm[8] * p23);
        float s33 = b2 * b2 * p33 + qv3;

        // ================= Regime 1 (rank-3 Woodbury; F1 = W S3 W^T + D) =================
        // Ntil = I + S3 * diag(G)
        float N00 = 1.f + s00 * G0, N01 = s01 * G1, N02 = s02 * G2;
        float N10 = s01 * G0, N11 = 1.f + s11 * G1, N12 = s12 * G2;
        float N20 = s02 * G0, N21 = s12 * G1, N22 = 1.f + s22 * G2;

        float c00 = N11 * N22 - N12 * N21;
        float c01 = N02 * N21 - N01 * N22;
        float c02 = N01 * N12 - N02 * N11;
        float c10 = N12 * N20 - N10 * N22;
        float c11 = N00 * N22 - N02 * N20;
        float c12 = N02 * N10 - N00 * N12;
        float c20 = N10 * N21 - N11 * N20;
        float c21 = N01 * N20 - N00 * N21;
        float c22 = N00 * N11 - N01 * N10;
        float det = N00 * c00 + N01 * c10 + N02 * c20;  // = det(F1)/det(D)
        float idet = 1.0f / det;

        // E = M^{-1} = Ntil^{-1} S3  (symmetric product)
        float E00 = (c00 * s00 + c01 * s01 + c02 * s02) * idet;
        float E01 = (c00 * s01 + c01 * s11 + c02 * s12) * idet;
        float E02 = (c00 * s02 + c01 * s12 + c02 * s22) * idet;
        float E10 = (c10 * s00 + c11 * s01 + c12 * s02) * idet;
        float E11 = (c10 * s01 + c11 * s11 + c12 * s12) * idet;
        float E12 = (c10 * s02 + c11 * s12 + c12 * s22) * idet;
        float E20 = (c20 * s00 + c21 * s01 + c22 * s02) * idet;
        float E21 = (c20 * s01 + c21 * s11 + c22 * s12) * idet;
        float E22 = (c20 * s02 + c21 * s12 + c22 * s22) * idet;

        // innovation v = y - L1 eta_pred (sparse)
        float v0 = yv[0] - ep0;
        float v1 = yv[1] - w1 * ep0;
        float v2 = yv[2] - w2 * ep0;
        float v3 = yv[3] - ep1;
        float v4 = yv[4] - w4 * ep1;
        float v5 = yv[5] - w5 * ep1;
        float v6 = yv[6] - ep2;
        float v7 = yv[7] - w7 * ep2;
        float v8 = yv[8] - w8 * ep2;

        float t0 = WD[0] * v0 + WD[1] * v1 + WD[2] * v2;
        float t1 = WD[3] * v3 + WD[4] * v4 + WD[5] * v5;
        float t2 = WD[6] * v6 + WD[7] * v7 + WD[8] * v8;

        float vDv = (v0 * Di[0]) * v0 + (v1 * Di[1]) * v1 + (v2 * Di[2]) * v2
                  + (v3 * Di[3]) * v3 + (v4 * Di[4]) * v4 + (v5 * Di[5]) * v5
                  + (v6 * Di[6]) * v6 + (v7 * Di[7]) * v7 + (v8 * Di[8]) * v8;

        float m0 = E00 * t0 + E01 * t1 + E02 * t2;
        float m1 = E10 * t0 + E11 * t1 + E12 * t2;
        float m2 = E20 * t0 + E21 * t1 + E22 * t2;
        float quad = t0 * m0 + t1 * m1 + t2 * m2;

        float ll1 = Cll - 0.5f * logf(det) - 0.5f * (vDv - quad);

        // J = I - diag(G) * E
        float J00 = 1.f - G0 * E00, J01 = -G0 * E01, J02 = -G0 * E02;
        float J10 = -G1 * E10, J11 = 1.f - G1 * E11, J12 = -G1 * E12;
        float J20 = -G2 * E20, J21 = -G2 * E21, J22 = 1.f - G2 * E22;

        // H = C * J, with C = P_pred[:, :3]
        float H00 = s00 * J00 + s01 * J10 + s02 * J20;
        float H01 = s00 * J01 + s01 * J11 + s02 * J21;
        float H02 = s00 * J02 + s01 * J12 + s02 * J22;
        float H10 = s01 * J00 + s11 * J10 + s12 * J20;
        float H11 = s01 * J01 + s11 * J11 + s12 * J21;
        float H12 = s01 * J02 + s11 * J12 + s12 * J22;
        float H20 = s02 * J00 + s12 * J10 + s22 * J20;
        float H21 = s02 * J01 + s12 * J11 + s22 * J21;
        float H22 = s02 * J02 + s12 * J12 + s22 * J22;
        float H30 = s03 * J00 + s13 * J10 + s23 * J20;
        float H31 = s03 * J01 + s13 * J11 + s23 * J21;
        float H32 = s03 * J02 + s13 * J12 + s23 * J22;

        // eta1 = eta_pred + K v = eta_pred + H t
        float q10 = ep0 + H00 * t0 + H01 * t1 + H02 * t2;
        float q11 = ep1 + H10 * t0 + H11 * t1 + H12 * t2;
        float q12 = ep2 + H20 * t0 + H21 * t1 + H22 * t2;
        float q13 = ep3 + H30 * t0 + H31 * t1 + H32 * t2;

        // HG = H * diag(G)  (K L1 = [HG | 0])
        float HG00 = H00 * G0, HG01 = H01 * G1, HG02 = H02 * G2;
        float HG10 = H10 * G0, HG11 = H11 * G1, HG12 = H12 * G2;
        float HG20 = H20 * G0, HG21 = H21 * G1, HG22 = H22 * G2;
        float HG30 = H30 * G0, HG31 = H31 * G1, HG32 = H32 * G2;

        // AP = (I - [HG|0]) P_pred   (full 4x4)
        float AP00 = s00 - (HG00 * s00 + HG01 * s01 + HG02 * s02);
        float AP01 = s01 - (HG00 * s01 + HG01 * s11 + HG02 * s12);
        float AP02 = s02 - (HG00 * s02 + HG01 * s12 + HG02 * s22);
        float AP03 = s03 - (HG00 * s03 + HG01 * s13 + HG02 * s23);
        float AP10 = s01 - (HG10 * s00 + HG11 * s01 + HG12 * s02);
        float AP11 = s11 - (HG10 * s01 + HG11 * s11 + HG12 * s12);
        float AP12 = s12 - (HG10 * s02 + HG11 * s12 + HG12 * s22);
        float AP13 = s13 - (HG10 * s03 + HG11 * s13 + HG12 * s23);
        float AP20 = s02 - (HG20 * s00 + HG21 * s01 + HG22 * s02);
        float AP21 = s12 - (HG20 * s01 + HG21 * s11 + HG22 * s12);
        float AP22 = s22 - (HG20 * s02 + HG21 * s12 + HG22 * s22);
        float AP23 = s23 - (HG20 * s03 + HG21 * s13 + HG22 * s23);
        float AP30 = s03 - (HG30 * s00 + HG31 * s01 + HG32 * s02);
        float AP31 = s13 - (HG30 * s01 + HG31 * s11 + HG32 * s12);
        float AP32 = s23 - (HG30 * s02 + HG31 * s12 + HG32 * s22);
        float AP33 = s33 - (HG30 * s03 + HG31 * s13 + HG32 * s23);

        // Hgr = H * diag(GR)  (K R K^T = Hgr H^T)
        float Hr00 = H00 * GR0, Hr01 = H01 * GR1, Hr02 = H02 * GR2;
        float Hr10 = H10 * GR0, Hr11 = H11 * GR1, Hr12 = H12 * GR2;
        float Hr20 = H20 * GR0, Hr21 = H21 * GR1, Hr22 = H22 * GR2;
        float Hr30 = H30 * GR0, Hr31 = H31 * GR1, Hr32 = H32 * GR2;

        // P1 = AP A^T + Hgr H^T (upper triangle; symmetric)
        float P1_00 = AP00 - (AP00 * HG00 + AP01 * HG01 + AP02 * HG02) + (Hr00 * H00 + Hr01 * H01 + Hr02 * H02);
        float P1_01 = AP01 - (AP00 * HG10 + AP01 * HG11 + AP02 * HG12) + (Hr00 * H10 + Hr01 * H11 + Hr02 * H12);
        float P1_02 = AP02 - (AP00 * HG20 + AP01 * HG21 + AP02 * HG22) + (Hr00 * H20 + Hr01 * H21 + Hr02 * H22);
        float P1_03 = AP03 - (AP00 * HG30 + AP01 * HG31 + AP02 * HG32) + (Hr00 * H30 + Hr01 * H31 + Hr02 * H32);
        float P1_11 = AP11 - (AP10 * HG10 + AP11 * HG11 + AP12 * HG12) + (Hr10 * H10 + Hr11 * H11 + Hr12 * H12);
        float P1_12 = AP12 - (AP10 * HG20 + AP11 * HG21 + AP12 * HG22) + (Hr10 * H20 + Hr11 * H21 + Hr12 * H22);
        float P1_13 = AP13 - (AP10 * HG30 + AP11 * HG31 + AP12 * HG32) + (Hr10 * H30 + Hr11 * H31 + Hr12 * H32);
        float P1_22 = AP22 - (AP20 * HG20 + AP21 * HG21 + AP22 * HG22) + (Hr20 * H20 + Hr21 * H21 + Hr22 * H22);
        float P1_23 = AP23 - (AP20 * HG30 + AP21 * HG31 + AP22 * HG32) + (Hr20 * H30 + Hr21 * H31 + Hr22 * H32);
        float P1_33 = AP33 - (AP30 * HG30 + AP31 * HG31 + AP32 * HG32) + (Hr30 * H30 + Hr31 * H31 + Hr32 * H32);

        // ================= Regime 2 (rank-1 Sherman-Morrison; F2 = s*u u^T + D) =================
        float sP = s33;
        float beta = 1.0f + sP * alpha;
        float binv = 1.0f / beta;

        float z0 = yv[0] - ep3;            // u[0] = 1
        float z1 = yv[1] - u[1] * ep3;
        float z2 = yv[2] - u[2] * ep3;
        float z3 = yv[3] - u[3] * ep3;
        float z4 = yv[4] - u[4] * ep3;
        float z5 = yv[5] - u[5] * ep3;
        float z6 = yv[6] - u[6] * ep3;
        float z7 = yv[7] - u[7] * ep3;
        float z8 = yv[8] - u[8] * ep3;

        float tau = du[0] * z0 + du[1] * z1 + du[2] * z2 + du[3] * z3 + du[4] * z4
                  + du[5] * z5 + du[6] * z6 + du[7] * z7 + du[8] * z8;
        float vDv2 = (z0 * Di[0]) * z0 + (z1 * Di[1]) * z1 + (z2 * Di[2]) * z2
                   + (z3 * Di[3]) * z3 + (z4 * Di[4]) * z4 + (z5 * Di[5]) * z5
                   + (z6 * Di[6]) * z6 + (z7 * Di[7]) * z7 + (z8 * Di[8]) * z8;

        float ll2 = Cll - 0.5f * logf(beta) - 0.5f * (vDv2 - sP * tau * tau * binv);

        float gk = tau * binv;
        float q20 = ep0 + s03 * gk;
        float q21 = ep1 + s13 * gk;
        float q22 = ep2 + s23 * gk;
        float q23 = ep3 + s33 * gk;

        float cc = alpha * binv;
        float kap = cc * (2.0f - cc * sP) - rho * binv * binv;
        // P2 = P_pred - kap * p p^T,  p = P_pred[:,3]
        float P2_00 = s00 - kap * s03 * s03;
        float P2_01 = s01 - kap * s03 * s13;
        float P2_02 = s02 - kap * s03 * s23;
        float P2_03 = s03 - kap * s03 * s33;
        float P2_11 = s11 - kap * s13 * s13;
        float P2_12 = s12 - kap * s13 * s23;
        float P2_13 = s13 - kap * s13 * s33;
        float P2_22 = s22 - kap * s23 * s23;
        float P2_23 = s23 - kap * s23 * s33;
        float P2_33 = s33 - kap * s33 * s33;

        // ================= IMM mixing =================
        float el1 = expf(ll1);
        float el2 = expf(ll2);
        float num1 = el1 * (pr0v * p11s);
        float num2 = el2 * (pr0v * (1.0f - p11s) + pr1v);
        float marg = num1 + num2 + 1e-9f;
        llacc += logf(marg);
        float im = 1.0f / marg;
        float pa = num1 * im;
        float pb = num2 * im;

        float x0 = pa * q10 + pb * q20;
        float x1 = pa * q11 + pb * q21;
        float x2 = pa * q12 + pb * q22;
        float x3 = pa * q13 + pb * q23;

        float d10 = q10 - x0, d11 = q11 - x1, d12 = q12 - x2, d13 = q13 - x3;
        float d20 = q20 - x0, d21 = q21 - x1, d22 = q22 - x2, d23 = q23 - x3;

        p00  = pa * (P1_00 + d10 * d10) + pb * (P2_00 + d20 * d20);
        p01  = pa * (P1_01 + d10 * d11) + pb * (P2_01 + d20 * d21);
        p02  = pa * (P1_02 + d10 * d12) + pb * (P2_02 + d20 * d22);
        p03  = pa * (P1_03 + d10 * d13) + pb * (P2_03 + d20 * d23);
        p11v = pa * (P1_11 + d11 * d11) + pb * (P2_11 + d21 * d21);
        p12  = pa * (P1_12 + d11 * d12) + pb * (P2_12 + d21 * d22);
        p13  = pa * (P1_13 + d11 * d13) + pb * (P2_13 + d21 * d23);
        p22  = pa * (P1_22 + d12 * d12) + pb * (P2_22 + d22 * d22);
        p23  = pa * (P1_23 + d12 * d13) + pb * (P2_23 + d22 * d23);
        p33  = pa * (P1_33 + d13 * d13) + pb * (P2_33 + d23 * d23);

        // ------------- outputs -------------
        size_t idx = (size_t)n * NTT + t;
        probs_base[idx * 2]     = pa;
        probs_base[idx * 2 + 1] = pb;

        float* yo = yp_base + idx * 9;
        float pe0 = pa * x0, pe1 = pa * x1, pe2 = pa * x2;
        float a3 = pb * x3;
        yo[0] = pe0 + a3;
        yo[1] = w1 * pe0 + u[1] * a3;
        yo[2] = w2 * pe0 + u[2] * a3;
        yo[3] = pe1 + u[3] * a3;
        yo[4] = w4 * pe1 + u[4] * a3;
        yo[5] = w5 * pe1 + u[5] * a3;
        yo[6] = pe2 + u[6] * a3;
        yo[7] = w7 * pe2 + u[7] * a3;
        yo[8] = w8 * pe2 + u[8] * a3;

        // commit state
        e0 = x0; e1 = x1; e2 = x2; e3 = x3;
        pr0v = pa; pr1v = pb;
#pragma unroll
        for (int o = 0; o < 9; o++) yv[o] = yn[o];
    }

    g_ll[n] = llacc;
}

// Deterministic fixed-order reduction of per-series log-likelihoods.
__global__ void reduce_ll(float* __restrict__ out)
{
    __shared__ double sh[256];
    int t = threadIdx.x;
    double a = 0.0;
#pragma unroll
    for (int i = 0; i < 16; i++) a += (double)g_ll[t * 16 + i];
    sh[t] = a;
    __syncthreads();
#pragma unroll
    for (int s = 128; s > 0; s >>= 1) {
        if (t < s) sh[t] += sh[t + s];
        __syncthreads();
    }
    if (t == 0) out[0] = (float)(-sh[0]);
}

extern "C" void kernel_launch(void* const* d_in, const int* in_sizes, int n_in,
                              void* d_out, int out_size)
{
    (void)in_sizes; (void)n_in; (void)out_size;
    const float* y    = (const float*)d_in[0];
    const float* B1s1 = (const float*)d_in[1];
    const float* B1s2 = (const float*)d_in[2];
    const float* l1f  = (const float*)d_in[3];
    const float* l2f  = (const float*)d_in[4];
    const float* logq = (const float*)d_in[5];
    const float* logr = (const float*)d_in[6];
    const float* g0   = (const float*)d_in[7];
    const float* gc   = (const float*)d_in[8];
    float* out = (float*)d_out;

    kf_kernel<<<NSER / 32, 32>>>(y, B1s1, B1s2, l1f, l2f, logq, logr, g0, gc, out);
    reduce_ll<<<1, 256>>>(out);
}